// round 3
// baseline (speedup 1.0000x reference)
#include <cuda_runtime.h>

#define HW_DIM 10
#define NUM_DEV 50
#define NUM_INT 101
#define ODIM 30

// One CTA per candidate interval. Block b speculatively prefetches the gather
// rows for interval b (addresses independent of x), computes the gate softmax,
// and writes the output only if round(x*100) == b. This removes the
// x -> idx -> gather serialized dependency from the critical path entirely.
__global__ __launch_bounds__(32, 1)
void mhn_kernel(const float* __restrict__ x,
                const float* __restrict__ hw,
                const float* __restrict__ hw_emb,
                const float* __restrict__ expert_emb,
                float* __restrict__ out)
{
    const int b    = blockIdx.x;   // candidate interval index
    const int lane = threadIdx.x;
    const unsigned full = 0xffffffffu;

    // ---- Chain A: speculative gather for interval b (starts at cycle 0) ----
    const int d = (lane < ODIM) ? lane : 0;      // lanes 30,31 harmless dup
    const float* gbase = expert_emb + (size_t)b * ODIM + d;
    float v[NUM_DEV];
#pragma unroll
    for (int e = 0; e < NUM_DEV; ++e)
        v[e] = __ldg(gbase + (size_t)e * (NUM_INT * ODIM));

    // ---- Chain B: x (only gates the final write) ----
    const float xv = __ldg(x);

    // ---- Chain C: hw gate computation ----
    float h[HW_DIM], he0[HW_DIM], he1[HW_DIM];
#pragma unroll
    for (int j = 0; j < HW_DIM; ++j) h[j] = __ldg(hw + j);

    const float* p0 = hw_emb + lane * HW_DIM;
#pragma unroll
    for (int j = 0; j < HW_DIM; ++j) he0[j] = __ldg(p0 + j);

    const int  e1i  = lane + 32;
    const bool has1 = (e1i < NUM_DEV);
    const float* p1 = hw_emb + (has1 ? e1i : 0) * HW_DIM;
#pragma unroll
    for (int j = 0; j < HW_DIM; ++j) he1[j] = __ldg(p1 + j);

    const float inv_sqrt = 0.31622776601683794f; // 1/sqrt(10)
    float d0 = 0.f, d1 = 0.f;
#pragma unroll
    for (int j = 0; j < HW_DIM; ++j) {
        d0 = fmaf(h[j], he0[j], d0);
        d1 = fmaf(h[j], he1[j], d1);
    }
    // sin in [-1,1] -> exp safe without max-subtraction; identical softmax.
    const float g0 = __expf(__sinf(d0 * inv_sqrt));
    const float g1 = has1 ? __expf(__sinf(d1 * inv_sqrt)) : 0.f;

    // ---- Combine with FUSED softmax sum (no serial shuffle reduction) ----
    float accA = 0.f, accB = 0.f, sA = 0.f, sB = 0.f;
#pragma unroll
    for (int e = 0; e < 32; e += 2) {
        const float ga = __shfl_sync(full, g0, e);
        const float gb = __shfl_sync(full, g0, e + 1);
        accA = fmaf(ga, v[e],     accA);  sA += ga;
        accB = fmaf(gb, v[e + 1], accB);  sB += gb;
    }
#pragma unroll
    for (int e = 32; e < NUM_DEV; e += 2) {
        const float ga = __shfl_sync(full, g1, e - 32);
        const float gb = __shfl_sync(full, g1, e - 31);
        accA = fmaf(ga, v[e],     accA);  sA += ga;
        accB = fmaf(gb, v[e + 1], accB);  sB += gb;
    }

    // ---- Predicated write: only the block matching idx writes ----
    const int idx = (int)rintf(xv * (float)(NUM_INT - 1));
    if (idx == b && lane < ODIM)
        out[lane] = __fdividef(accA + accB, sA + sB);
}

extern "C" void kernel_launch(void* const* d_in, const int* in_sizes, int n_in,
                              void* d_out, int out_size)
{
    const float* x          = (const float*)d_in[0];
    const float* hw         = (const float*)d_in[1];
    const float* hw_emb     = (const float*)d_in[2];
    const float* expert_emb = (const float*)d_in[3];
    float* out = (float*)d_out;

    mhn_kernel<<<NUM_INT, 32>>>(x, hw, hw_emb, expert_emb, out);
}

// round 4
// speedup vs baseline: 1.0372x; 1.0372x over previous
#include <cuda_runtime.h>

#define HW_DIM 10
#define NUM_DEV 50
#define NUM_INT 101
#define ODIM 30

__global__ __launch_bounds__(32, 1)
void mhn_kernel(const float* __restrict__ x,
                const float* __restrict__ hw,
                const float* __restrict__ hw_emb,
                const float* __restrict__ expert_emb,
                float* __restrict__ out)
{
    const int lane = threadIdx.x;
    __shared__ float4 gate4[13];   // 52 gates; [50],[51] zero-padded

    // ---- Root of chain A: x (gates the gather addresses) ----
    const float xv = __ldg(x);

    // ---- Chain B loads (issue while x is in flight): hw + 2 hw_emb rows ----
    // hw: 40B from a 256B-aligned allocation -> float4 x2 + float2
    float h[HW_DIM];
    {
        const float4 h0 = __ldg((const float4*)hw);
        const float4 h1 = __ldg((const float4*)(hw + 4));
        const float2 h2 = __ldg((const float2*)(hw + 8));
        h[0]=h0.x; h[1]=h0.y; h[2]=h0.z; h[3]=h0.w;
        h[4]=h1.x; h[5]=h1.y; h[6]=h1.z; h[7]=h1.w;
        h[8]=h2.x; h[9]=h2.y;
    }
    // hw_emb rows: 40B each, 8B-aligned -> 5x float2 per row
    float he0[HW_DIM], he1[HW_DIM];
    {
        const float2* p0 = (const float2*)(hw_emb + lane * HW_DIM);
#pragma unroll
        for (int j = 0; j < 5; ++j) { float2 t = __ldg(p0 + j); he0[2*j] = t.x; he0[2*j+1] = t.y; }
    }
    const int  e1i  = lane + 32;
    const bool has1 = (e1i < NUM_DEV);
    {
        const float2* p1 = (const float2*)(hw_emb + (has1 ? e1i : 0) * HW_DIM);
#pragma unroll
        for (int j = 0; j < 5; ++j) { float2 t = __ldg(p1 + j); he1[2*j] = t.x; he1[2*j+1] = t.y; }
    }

    // ---- Chain A continuation: idx -> 50 gather loads into registers ----
    const int idx = (int)rintf(xv * (float)(NUM_INT - 1));
    const int d = (lane < ODIM) ? lane : 0;          // lanes 30,31 harmless dup
    const float* gbase = expert_emb + (size_t)idx * ODIM + d;
    float v[NUM_DEV];
#pragma unroll
    for (int e = 0; e < NUM_DEV; ++e)
        v[e] = __ldg(gbase + (size_t)e * (NUM_INT * ODIM));

    // ---- Chain B compute: dot -> sin -> exp (sin in [-1,1]: no max-sub) ----
    const float inv_sqrt = 0.31622776601683794f;     // 1/sqrt(10)
    float d0 = 0.f, d1 = 0.f;
#pragma unroll
    for (int j = 0; j < HW_DIM; ++j) {
        d0 = fmaf(h[j], he0[j], d0);
        d1 = fmaf(h[j], he1[j], d1);
    }
    const float g0 = __expf(__sinf(d0 * inv_sqrt));
    const float g1 = has1 ? __expf(__sinf(d1 * inv_sqrt)) : 0.f;

    // ---- Publish gates to shared (incl. zero pad), one barrier ----
    float* gs = (float*)gate4;
    gs[lane] = g0;
    if (lane < 20) gs[lane + 32] = (lane < 18) ? g1 : 0.f;  // 50,51 = 0 pad
    __syncwarp();

    // ---- Combine with fused softmax sum; float4 broadcast reads ----
    float accA = 0.f, accB = 0.f, sA = 0.f, sB = 0.f;
#pragma unroll
    for (int i = 0; i < 12; ++i) {
        const float4 g = gate4[i];
        accA = fmaf(g.x, v[4*i+0], accA);  sA += g.x;
        accB = fmaf(g.y, v[4*i+1], accB);  sB += g.y;
        accA = fmaf(g.z, v[4*i+2], accA);  sA += g.z;
        accB = fmaf(g.w, v[4*i+3], accB);  sB += g.w;
    }
    {   // tail: e = 48,49 (g.z, g.w are the zero pads)
        const float4 g = gate4[12];
        accA = fmaf(g.x, v[48], accA);  sA += g.x;
        accB = fmaf(g.y, v[49], accB);  sB += g.y;
    }

    if (lane < ODIM)
        out[lane] = __fdividef(accA + accB, sA + sB);
}

extern "C" void kernel_launch(void* const* d_in, const int* in_sizes, int n_in,
                              void* d_out, int out_size)
{
    const float* x          = (const float*)d_in[0];
    const float* hw         = (const float*)d_in[1];
    const float* hw_emb     = (const float*)d_in[2];
    const float* expert_emb = (const float*)d_in[3];
    float* out = (float*)d_out;

    mhn_kernel<<<1, 32>>>(x, hw, hw_emb, expert_emb, out);
}

// round 5
// speedup vs baseline: 1.0773x; 1.0386x over previous
#include <cuda_runtime.h>

#define HW_DIM 10
#define NUM_DEV 50
#define NUM_INT 101
#define ODIM 30

// 2 warps, split by expert: warp w owns experts [25w, 25w+25).
// Each warp: 25 gather LDGs (half issue train), 1 dot+sinf+expf per lane
// (half MUFU chain), 25-FMA combine (half serial chain). Warps are fully
// independent until one final __syncthreads + cross-warp add.
__global__ __launch_bounds__(64, 1)
void mhn_kernel(const float* __restrict__ x,
                const float* __restrict__ hw,
                const float* __restrict__ hw_emb,
                const float* __restrict__ expert_emb,
                float* __restrict__ out)
{
    const int tid  = threadIdx.x;
    const int w    = tid >> 5;          // warp id: 0 or 1
    const int lane = tid & 31;

    __shared__ float gs[64];            // gates, indexed w*32 + j (j<25 valid)
    __shared__ float accsh[64];         // per-warp partial outputs
    __shared__ float ssh[2];            // per-warp partial softmax sums

    // ---- Chain A root: x, issued first ----
    const float xv = __ldg(x);

    // ---- Chain B loads: hw (vectorized) + ONE hw_emb row per lane ----
    float h[HW_DIM];
    {
        const float4 h0 = __ldg((const float4*)hw);
        const float4 h1 = __ldg((const float4*)(hw + 4));
        const float2 h2 = __ldg((const float2*)(hw + 8));
        h[0]=h0.x; h[1]=h0.y; h[2]=h0.z; h[3]=h0.w;
        h[4]=h1.x; h[5]=h1.y; h[6]=h1.z; h[7]=h1.w;
        h[8]=h2.x; h[9]=h2.y;
    }
    const int  eg   = w * 25 + ((lane < 25) ? lane : 0);  // gate expert (dup masked)
    float he[HW_DIM];
    {
        const float2* p = (const float2*)(hw_emb + eg * HW_DIM);
#pragma unroll
        for (int j = 0; j < 5; ++j) { float2 t = __ldg(p + j); he[2*j] = t.x; he[2*j+1] = t.y; }
    }

    // ---- Chain A: idx -> 25 gather loads per warp ----
    const int idx = __float2int_rn(xv * (float)(NUM_INT - 1));
    const int d   = (lane < ODIM) ? lane : 0;            // lanes 30,31 harmless dup
    const float* gbase = expert_emb
                       + (size_t)(w * 25) * (NUM_INT * ODIM)
                       + (size_t)idx * ODIM + d;
    float v[25];
#pragma unroll
    for (int j = 0; j < 25; ++j)
        v[j] = __ldg(gbase + (size_t)j * (NUM_INT * ODIM));

    // ---- Chain B compute: one dot -> sin -> exp per lane ----
    const float inv_sqrt = 0.31622776601683794f;         // 1/sqrt(10)
    float dt0 = 0.f, dt1 = 0.f;
#pragma unroll
    for (int j = 0; j < 5; ++j) {
        dt0 = fmaf(h[2*j],   he[2*j],   dt0);
        dt1 = fmaf(h[2*j+1], he[2*j+1], dt1);
    }
    const float g = __expf(__sinf((dt0 + dt1) * inv_sqrt));

    // Publish own-warp gates; each warp only reads gates it wrote -> syncwarp.
    if (lane < 25) gs[w * 32 + lane] = g;
    __syncwarp();

    // ---- Per-warp combine with fused partial softmax sum ----
    float accA = 0.f, accB = 0.f, sA = 0.f, sB = 0.f;
    const float* gw = gs + w * 32;
#pragma unroll
    for (int j = 0; j < 24; j += 2) {
        const float ga = gw[j], gb = gw[j + 1];
        accA = fmaf(ga, v[j],     accA);  sA += ga;
        accB = fmaf(gb, v[j + 1], accB);  sB += gb;
    }
    {   const float ga = gw[24];
        accA = fmaf(ga, v[24], accA);  sA += ga; }

    accsh[tid] = accA + accB;
    if (lane == 0) ssh[w] = sA + sB;
    __syncthreads();

    // ---- Warp 0 merges the two partials and writes out ----
    if (tid < ODIM)
        out[tid] = __fdividef(accsh[tid] + accsh[tid + 32], ssh[0] + ssh[1]);
}

extern "C" void kernel_launch(void* const* d_in, const int* in_sizes, int n_in,
                              void* d_out, int out_size)
{
    const float* x          = (const float*)d_in[0];
    const float* hw         = (const float*)d_in[1];
    const float* hw_emb     = (const float*)d_in[2];
    const float* expert_emb = (const float*)d_in[3];
    float* out = (float*)d_out;

    mhn_kernel<<<1, 64>>>(x, hw, hw_emb, expert_emb, out);
}